// round 4
// baseline (speedup 1.0000x reference)
#include <cuda_runtime.h>
#include <math.h>

// ---------------- problem constants ----------------
#define NLEV   16
#define TBL    524288u          // T = 2^19 entries per level
#define TMASK  (TBL - 1u)
#define HP1    2654435761u
#define HP2    805459861u

#define CAP    2097152          // expected N
#define KBITS  18
#define BINS   (1u << KBITS)    // 262144 morton buckets
#define TILE   1024             // scan tile
#define NTILES (BINS / TILE)    // 256

typedef unsigned long long ull;

// MLP weights in constant memory (warp-uniform -> LDCU, keeps LSU free)
__constant__ __align__(16) float cW1[32 * 64];
__constant__ __align__(16) float cW2[64 * 16];

// ---- static scratch (no dynamic allocation allowed) ----
__device__ unsigned g_keys[CAP];
__device__ unsigned g_perm[CAP];
__device__ float    g_sx[CAP];
__device__ float    g_sy[CAP];
__device__ float    g_sz[CAP];
__device__ unsigned g_hist[BINS];
__device__ unsigned g_offs[BINS];
__device__ unsigned g_part[NTILES];

struct LevelParams {
    float    resf[NLEV];   // (float)res[l]
    unsigned s[NLEV];      // res[l] + 1  (dense stride)
    unsigned dense[NLEV];  // (res+1)^3 <= T ?
};

// ---------------- packed f32x2 helpers ----------------
__device__ __forceinline__ ull pack2(float v) {
    ull r; unsigned u = __float_as_uint(v);
    asm("mov.b64 %0, {%1,%1};" : "=l"(r) : "r"(u));
    return r;
}
__device__ __forceinline__ ull fma2(ull a, ull b, ull c) {
    ull d;
    asm("fma.rn.f32x2 %0, %1, %2, %3;" : "=l"(d) : "l"(a), "l"(b), "l"(c));
    return d;
}
__device__ __forceinline__ float2 unpack2(ull v) {
    unsigned lo, hi;
    asm("mov.b64 {%0,%1}, %2;" : "=r"(lo), "=r"(hi) : "l"(v));
    return make_float2(__uint_as_float(lo), __uint_as_float(hi));
}

// Dual-path paired gather, alignment-safe.
// adj != 0 (i.e. (a0^a1)==1): both entries live in the SAME aligned 16B block
// at (a0 & ~1) -> one LDG.128; halves swizzled by parity of a0 afterward.
// adj == 0: two LDG.64. Predicated: inactive path emits no wavefronts.
__device__ __forceinline__ void gather_pair(const float2* __restrict__ tab,
                                            unsigned a0, unsigned a1,
                                            unsigned adj,
                                            float& v0x, float& v0y,
                                            float& v1x, float& v1y) {
    const float4* pa = reinterpret_cast<const float4*>(tab + (a0 & ~1u));
    float qx, qy, qz, qw;
    asm volatile("{\n\t"
                 ".reg .pred p;\n\t"
                 "setp.ne.u32 p, %4, 0;\n\t"
                 "@p  ld.global.nc.v4.f32 {%0,%1,%2,%3}, [%5];\n\t"
                 "@!p ld.global.nc.v2.f32 {%0,%1}, [%6];\n\t"
                 "@!p ld.global.nc.v2.f32 {%2,%3}, [%7];\n\t"
                 "}"
                 : "=f"(qx), "=f"(qy), "=f"(qz), "=f"(qw)
                 : "r"(adj), "l"(pa), "l"(tab + a0), "l"(tab + a1));
    // swap halves only when the 128-bit path was taken AND a0 is odd
    bool swap = (adj != 0u) && ((a0 & 1u) != 0u);
    v0x = swap ? qz : qx;
    v0y = swap ? qw : qy;
    v1x = swap ? qx : qz;
    v1y = swap ? qy : qw;
}

// ---------------- morton ----------------
__device__ __forceinline__ unsigned part1by2(unsigned x) {
    x &= 0x3ffu;
    x = (x | (x << 16)) & 0x030000FFu;
    x = (x | (x << 8))  & 0x0300F00Fu;
    x = (x | (x << 4))  & 0x030C30C3u;
    x = (x | (x << 2))  & 0x09249249u;
    return x;
}
__device__ __forceinline__ float clip01(float v) {
    return fminf(fmaxf((v + 1.0f) * 0.5f, 0.0f), 1.0f);
}
__device__ __forceinline__ unsigned morton_key(float x, float y, float z) {
    unsigned ix = min((unsigned)(clip01(x) * 64.0f), 63u);
    unsigned iy = min((unsigned)(clip01(y) * 64.0f), 63u);
    unsigned iz = min((unsigned)(clip01(z) * 64.0f), 63u);
    return part1by2(ix) | (part1by2(iy) << 1) | (part1by2(iz) << 2);
}

// ---------------- sort pipeline (5 launches) ----------------
__global__ void k_zero_hist() {
    unsigned g = blockIdx.x * blockDim.x + threadIdx.x;
    if (g < BINS) g_hist[g] = 0u;
}

__global__ void k_keys_hist(const float* __restrict__ xyzs, int N) {
    int i = blockIdx.x * blockDim.x + threadIdx.x;
    if (i >= N) return;
    unsigned k = morton_key(xyzs[3 * i], xyzs[3 * i + 1], xyzs[3 * i + 2]);
    g_keys[i] = k;
    atomicAdd(&g_hist[k], 1u);
}

__global__ void k_scan_tiles() {
    __shared__ unsigned sm[TILE];
    unsigned t = threadIdx.x;
    unsigned g = blockIdx.x * TILE + t;
    unsigned v = g_hist[g];
    sm[t] = v;
    __syncthreads();
#pragma unroll
    for (unsigned d = 1; d < TILE; d <<= 1) {
        unsigned add = (t >= d) ? sm[t - d] : 0u;
        __syncthreads();
        sm[t] += add;
        __syncthreads();
    }
    g_offs[g] = sm[t] - v;           // tile-local exclusive
    if (t == TILE - 1) g_part[blockIdx.x] = sm[t];
}

__global__ void k_scan_part() {
    __shared__ unsigned sm[NTILES];
    unsigned t = threadIdx.x;
    unsigned v = g_part[t];
    sm[t] = v;
    __syncthreads();
#pragma unroll
    for (unsigned d = 1; d < NTILES; d <<= 1) {
        unsigned add = (t >= d) ? sm[t - d] : 0u;
        __syncthreads();
        sm[t] += add;
        __syncthreads();
    }
    g_part[t] = sm[t] - v;           // exclusive tile bases
}

// addback fused here: final position = tile_base + tile_local_offset
__global__ void k_scatter(const float* __restrict__ xyzs, int N) {
    int i = blockIdx.x * blockDim.x + threadIdx.x;
    if (i >= N) return;
    unsigned k   = g_keys[i];
    unsigned pos = atomicAdd(&g_offs[k], 1u) + g_part[k >> 10];
    g_perm[pos] = (unsigned)i;
    g_sx[pos] = xyzs[3 * i];
    g_sy[pos] = xyzs[3 * i + 1];
    g_sz[pos] = xyzs[3 * i + 2];
}

// ---------------- fused kernel: hashgrid encode + MLP ----------------
__global__ void __launch_bounds__(256)
hashgrid_mlp_kernel(const float* __restrict__ xyzs,
                    const float* __restrict__ tables,
                    float* __restrict__ out,
                    int N, int use_perm, LevelParams lp)
{
    int i = blockIdx.x * blockDim.x + threadIdx.x;
    if (i >= N) return;

    int pid;
    float x, y, z;
    if (use_perm) {
        pid = (int)g_perm[i];
        x = g_sx[i]; y = g_sy[i]; z = g_sz[i];
    } else {
        pid = i;
        x = xyzs[3 * i]; y = xyzs[3 * i + 1]; z = xyzs[3 * i + 2];
    }

    float x01 = clip01(x), y01 = clip01(y), z01 = clip01(z);

    float enc[32];

#pragma unroll
    for (int l = 0; l < NLEV; l++) {
        const float2* __restrict__ tab =
            reinterpret_cast<const float2*>(tables) + (size_t)l * TBL;

        float rf = lp.resf[l];
        float px = x01 * rf, py = y01 * rf, pz = z01 * rf;
        float fpx = floorf(px), fpy = floorf(py), fpz = floorf(pz);
        float fx = px - fpx, fy = py - fpy, fz = pz - fpz;
        unsigned ix = (unsigned)fpx, iy = (unsigned)fpy, iz = (unsigned)fpz;
        float wx0 = 1.0f - fx, wy0 = 1.0f - fy, wz0 = 1.0f - fz;

        unsigned i0a[4], i1a[4];
        float    wyz[4];
        if (lp.dense[l]) {
            unsigned s = lp.s[l];
#pragma unroll
            for (int k = 0; k < 2; k++) {
#pragma unroll
                for (int j = 0; j < 2; j++) {
                    unsigned a = s * ((iy + (unsigned)j) + s * (iz + (unsigned)k));
                    int c = k * 2 + j;
                    i0a[c] = ix + a;
                    i1a[c] = ix + 1u + a;
                    wyz[c] = (j ? fy : wy0) * (k ? fz : wz0);
                }
            }
        } else {
            unsigned hy0 = iy * HP1;
            unsigned hz0 = iz * HP2;
#pragma unroll
            for (int k = 0; k < 2; k++) {
#pragma unroll
                for (int j = 0; j < 2; j++) {
                    unsigned a = (hy0 + (j ? HP1 : 0u)) ^ (hz0 + (k ? HP2 : 0u));
                    int c = k * 2 + j;
                    i0a[c] = (ix ^ a) & TMASK;
                    i1a[c] = ((ix + 1u) ^ a) & TMASK;
                    wyz[c] = (j ? fy : wy0) * (k ? fz : wz0);
                }
            }
        }

        float v0x[4], v0y[4], v1x[4], v1y[4];
#pragma unroll
        for (int c = 0; c < 4; c++) {
            unsigned adj = ((i0a[c] ^ i1a[c]) == 1u) ? 1u : 0u;
            gather_pair(tab, i0a[c], i1a[c], adj,
                        v0x[c], v0y[c], v1x[c], v1y[c]);
        }

        float e0 = 0.0f, e1 = 0.0f;
#pragma unroll
        for (int c = 0; c < 4; c++) {
            float w0 = wx0 * wyz[c];
            float w1 = fx  * wyz[c];
            e0 = fmaf(w0, v0x[c], fmaf(w1, v1x[c], e0));
            e1 = fmaf(w0, v0y[c], fmaf(w1, v1y[c], e1));
        }
        enc[2 * l]     = e0;
        enc[2 * l + 1] = e1;
    }

    // ---------------- MLP layer 1: h = relu(enc @ W1) ----------------
    ull hp[32];
#pragma unroll
    for (int j = 0; j < 32; j++) hp[j] = 0ull;

#pragma unroll
    for (int i1 = 0; i1 < 32; i1++) {
        ull ee = pack2(enc[i1]);
        const ulonglong2* wrow =
            reinterpret_cast<const ulonglong2*>(cW1 + i1 * 64);
#pragma unroll
        for (int j = 0; j < 16; j++) {
            ulonglong2 w = wrow[j];
            hp[2 * j]     = fma2(ee, w.x, hp[2 * j]);
            hp[2 * j + 1] = fma2(ee, w.y, hp[2 * j + 1]);
        }
    }

    float h[64];
#pragma unroll
    for (int j = 0; j < 32; j++) {
        float2 p = unpack2(hp[j]);
        h[2 * j]     = fmaxf(p.x, 0.0f);
        h[2 * j + 1] = fmaxf(p.y, 0.0f);
    }

    // ---------------- MLP layer 2 ----------------
    ull op[8];
#pragma unroll
    for (int j = 0; j < 8; j++) op[j] = 0ull;
#pragma unroll
    for (int i2 = 0; i2 < 64; i2++) {
        ull ee = pack2(h[i2]);
        const ulonglong2* wrow =
            reinterpret_cast<const ulonglong2*>(cW2 + i2 * 16);
#pragma unroll
        for (int j = 0; j < 4; j++) {
            ulonglong2 w = wrow[j];
            op[2 * j]     = fma2(ee, w.x, op[2 * j]);
            op[2 * j + 1] = fma2(ee, w.y, op[2 * j + 1]);
        }
    }

    float o[16];
#pragma unroll
    for (int j = 0; j < 8; j++) {
        float2 p = unpack2(op[j]);
        o[2 * j]     = p.x;
        o[2 * j + 1] = p.y;
    }

    out[pid] = expf(o[0]);
    float* g = out + (size_t)N + (size_t)pid * 15;
#pragma unroll
    for (int k = 0; k < 15; k++) g[k] = o[k + 1];
}

// ---------------- host ----------------
static LevelParams make_level_params()
{
    LevelParams lp;
    double pls = exp(log(2048.0 / 16.0) / (double)(NLEV - 1));
    for (int l = 0; l < NLEV; l++) {
        int r = (int)ceil(16.0 * pow(pls, (double)l));
        lp.resf[l]  = (float)r;
        lp.s[l]     = (unsigned)(r + 1);
        long long s = (long long)(r + 1);
        lp.dense[l] = (s * s * s <= (long long)TBL) ? 1u : 0u;
    }
    return lp;
}

extern "C" void kernel_launch(void* const* d_in, const int* in_sizes, int n_in,
                              void* d_out, int out_size)
{
    (void)n_in; (void)out_size;
    const float* xyzs   = (const float*)d_in[0];
    const float* tables = (const float*)d_in[1];
    int N = in_sizes[0] / 3;

    cudaMemcpyToSymbolAsync(cW1, d_in[2], 32 * 64 * sizeof(float), 0,
                            cudaMemcpyDeviceToDevice, 0);
    cudaMemcpyToSymbolAsync(cW2, d_in[3], 64 * 16 * sizeof(float), 0,
                            cudaMemcpyDeviceToDevice, 0);

    LevelParams lp = make_level_params();

    int use_perm = (N <= CAP) ? 1 : 0;
    int blk = 256;
    int gridN = (N + blk - 1) / blk;

    // 5 sort launches + main => main is launch #6 (ncu -s 5 -c 1 lands on it)
    if (use_perm) {
        k_zero_hist<<<BINS / 256, 256>>>();
        k_keys_hist<<<gridN, blk>>>(xyzs, N);
        k_scan_tiles<<<NTILES, TILE>>>();
        k_scan_part<<<1, NTILES>>>();
        k_scatter<<<gridN, blk>>>(xyzs, N);
    }

    hashgrid_mlp_kernel<<<gridN, blk>>>(xyzs, tables, (float*)d_out,
                                        N, use_perm, lp);
}

// round 5
// speedup vs baseline: 1.2164x; 1.2164x over previous
#include <cuda_runtime.h>
#include <math.h>

// ---------------- problem constants ----------------
#define NLEV   16
#define TBL    524288u          // T = 2^19 entries per level
#define TMASK  (TBL - 1u)
#define HP1    2654435761u
#define HP2    805459861u

typedef unsigned long long ull;

// MLP weights in constant memory (warp-uniform -> LDCU, keeps LSU free)
__constant__ __align__(16) float cW1[32 * 64];
__constant__ __align__(16) float cW2[64 * 16];

struct LevelParams {
    float    resf[NLEV];   // (float)res[l]
    unsigned s[NLEV];      // res[l] + 1  (dense stride)
    unsigned dense[NLEV];  // (res+1)^3 <= T ?
};

// ---------------- packed f32x2 helpers ----------------
__device__ __forceinline__ ull pack2(float v) {
    ull r; unsigned u = __float_as_uint(v);
    asm("mov.b64 %0, {%1,%1};" : "=l"(r) : "r"(u));
    return r;
}
__device__ __forceinline__ ull fma2(ull a, ull b, ull c) {
    ull d;
    asm("fma.rn.f32x2 %0, %1, %2, %3;" : "=l"(d) : "l"(a), "l"(b), "l"(c));
    return d;
}
__device__ __forceinline__ float2 unpack2(ull v) {
    unsigned lo, hi;
    asm("mov.b64 {%0,%1}, %2;" : "=r"(lo), "=r"(hi) : "l"(v));
    return make_float2(__uint_as_float(lo), __uint_as_float(hi));
}

// Dual-path paired gather, alignment-safe (proven correct in round 4).
// adj != 0 ((a0^a1)==1): both entries live in the SAME aligned 16B block at
// (a0 & ~1) -> one LDG.128, halves swizzled by parity of a0.
// adj == 0: two LDG.64. Predicated: the inactive path emits no wavefronts.
__device__ __forceinline__ void gather_pair(const float2* __restrict__ tab,
                                            unsigned a0, unsigned a1,
                                            unsigned adj,
                                            float& v0x, float& v0y,
                                            float& v1x, float& v1y) {
    const float4* pa = reinterpret_cast<const float4*>(tab + (a0 & ~1u));
    float qx, qy, qz, qw;
    asm volatile("{\n\t"
                 ".reg .pred p;\n\t"
                 "setp.ne.u32 p, %4, 0;\n\t"
                 "@p  ld.global.nc.v4.f32 {%0,%1,%2,%3}, [%5];\n\t"
                 "@!p ld.global.nc.v2.f32 {%0,%1}, [%6];\n\t"
                 "@!p ld.global.nc.v2.f32 {%2,%3}, [%7];\n\t"
                 "}"
                 : "=f"(qx), "=f"(qy), "=f"(qz), "=f"(qw)
                 : "r"(adj), "l"(pa), "l"(tab + a0), "l"(tab + a1));
    bool swap = (adj != 0u) && ((a0 & 1u) != 0u);
    v0x = swap ? qz : qx;
    v0y = swap ? qw : qy;
    v1x = swap ? qx : qz;
    v1y = swap ? qy : qw;
}

__device__ __forceinline__ float clip01(float v) {
    return fminf(fmaxf((v + 1.0f) * 0.5f, 0.0f), 1.0f);
}

// ---------------- fused kernel: hashgrid encode + MLP ----------------
#define BLK 256

__global__ void __launch_bounds__(BLK)
hashgrid_mlp_kernel(const float* __restrict__ xyzs,
                    const float* __restrict__ tables,
                    float* __restrict__ out,
                    int N, LevelParams lp)
{
    __shared__ float sgeo[BLK * 15];   // staged geo rows for coalesced store

    int pid = blockIdx.x * BLK + threadIdx.x;
    bool active = (pid < N);

    float o[16];

    if (active) {
        float x = xyzs[3 * pid + 0];
        float y = xyzs[3 * pid + 1];
        float z = xyzs[3 * pid + 2];
        float x01 = clip01(x), y01 = clip01(y), z01 = clip01(z);

        float enc[32];

#pragma unroll
        for (int l = 0; l < NLEV; l++) {
            const float2* __restrict__ tab =
                reinterpret_cast<const float2*>(tables) + (size_t)l * TBL;

            float rf = lp.resf[l];
            float px = x01 * rf, py = y01 * rf, pz = z01 * rf;
            float fpx = floorf(px), fpy = floorf(py), fpz = floorf(pz);
            float fx = px - fpx, fy = py - fpy, fz = pz - fpz;
            unsigned ix = (unsigned)fpx, iy = (unsigned)fpy, iz = (unsigned)fpz;
            float wx0 = 1.0f - fx, wy0 = 1.0f - fy, wz0 = 1.0f - fz;

            unsigned i0a[4], i1a[4];
            float    wyz[4];
            if (lp.dense[l]) {
                unsigned s = lp.s[l];
#pragma unroll
                for (int k = 0; k < 2; k++) {
#pragma unroll
                    for (int j = 0; j < 2; j++) {
                        unsigned a = s * ((iy + (unsigned)j) + s * (iz + (unsigned)k));
                        int c = k * 2 + j;
                        i0a[c] = ix + a;
                        i1a[c] = ix + 1u + a;
                        wyz[c] = (j ? fy : wy0) * (k ? fz : wz0);
                    }
                }
            } else {
                unsigned hy0 = iy * HP1;
                unsigned hz0 = iz * HP2;
#pragma unroll
                for (int k = 0; k < 2; k++) {
#pragma unroll
                    for (int j = 0; j < 2; j++) {
                        unsigned a = (hy0 + (j ? HP1 : 0u)) ^ (hz0 + (k ? HP2 : 0u));
                        int c = k * 2 + j;
                        i0a[c] = (ix ^ a) & TMASK;
                        i1a[c] = ((ix + 1u) ^ a) & TMASK;
                        wyz[c] = (j ? fy : wy0) * (k ? fz : wz0);
                    }
                }
            }

            float v0x[4], v0y[4], v1x[4], v1y[4];
#pragma unroll
            for (int c = 0; c < 4; c++) {
                unsigned adj = ((i0a[c] ^ i1a[c]) == 1u) ? 1u : 0u;
                gather_pair(tab, i0a[c], i1a[c], adj,
                            v0x[c], v0y[c], v1x[c], v1y[c]);
            }

            float e0 = 0.0f, e1 = 0.0f;
#pragma unroll
            for (int c = 0; c < 4; c++) {
                float w0 = wx0 * wyz[c];
                float w1 = fx  * wyz[c];
                e0 = fmaf(w0, v0x[c], fmaf(w1, v1x[c], e0));
                e1 = fmaf(w0, v0y[c], fmaf(w1, v1y[c], e1));
            }
            enc[2 * l]     = e0;
            enc[2 * l + 1] = e1;
        }

        // MLP layer 1: h = relu(enc @ W1)
        ull hp[32];
#pragma unroll
        for (int j = 0; j < 32; j++) hp[j] = 0ull;
#pragma unroll
        for (int i1 = 0; i1 < 32; i1++) {
            ull ee = pack2(enc[i1]);
            const ulonglong2* wrow =
                reinterpret_cast<const ulonglong2*>(cW1 + i1 * 64);
#pragma unroll
            for (int j = 0; j < 16; j++) {
                ulonglong2 w = wrow[j];
                hp[2 * j]     = fma2(ee, w.x, hp[2 * j]);
                hp[2 * j + 1] = fma2(ee, w.y, hp[2 * j + 1]);
            }
        }

        float h[64];
#pragma unroll
        for (int j = 0; j < 32; j++) {
            float2 p = unpack2(hp[j]);
            h[2 * j]     = fmaxf(p.x, 0.0f);
            h[2 * j + 1] = fmaxf(p.y, 0.0f);
        }

        // MLP layer 2
        ull op[8];
#pragma unroll
        for (int j = 0; j < 8; j++) op[j] = 0ull;
#pragma unroll
        for (int i2 = 0; i2 < 64; i2++) {
            ull ee = pack2(h[i2]);
            const ulonglong2* wrow =
                reinterpret_cast<const ulonglong2*>(cW2 + i2 * 16);
#pragma unroll
            for (int j = 0; j < 4; j++) {
                ulonglong2 w = wrow[j];
                op[2 * j]     = fma2(ee, w.x, op[2 * j]);
                op[2 * j + 1] = fma2(ee, w.y, op[2 * j + 1]);
            }
        }

#pragma unroll
        for (int j = 0; j < 8; j++) {
            float2 p = unpack2(op[j]);
            o[2 * j]     = p.x;
            o[2 * j + 1] = p.y;
        }

        // sigma: coalesced scalar store
        out[pid] = expf(o[0]);
        // stage geo row in smem
#pragma unroll
        for (int k = 0; k < 15; k++)
            sgeo[threadIdx.x * 15 + k] = o[k + 1];
    }

    __syncthreads();

    // cooperative coalesced store of this block's geo region
    int base  = blockIdx.x * BLK;
    int nPts  = min(BLK, N - base);
    if (nPts <= 0) return;
    float* gbase = out + (size_t)N + (size_t)base * 15;
    int total = nPts * 15;
    if (nPts == BLK && ((((size_t)gbase) & 15u) == 0)) {
        float4* g4 = reinterpret_cast<float4*>(gbase);
        const float4* s4 = reinterpret_cast<const float4*>(sgeo);
        int n4 = total / 4;  // 960
        for (int t = threadIdx.x; t < n4; t += BLK) g4[t] = s4[t];
    } else {
        for (int t = threadIdx.x; t < total; t += BLK) gbase[t] = sgeo[t];
    }
}

// ---------------- host ----------------
static LevelParams make_level_params()
{
    LevelParams lp;
    double pls = exp(log(2048.0 / 16.0) / (double)(NLEV - 1));
    for (int l = 0; l < NLEV; l++) {
        int r = (int)ceil(16.0 * pow(pls, (double)l));
        lp.resf[l]  = (float)r;
        lp.s[l]     = (unsigned)(r + 1);
        long long s = (long long)(r + 1);
        lp.dense[l] = (s * s * s <= (long long)TBL) ? 1u : 0u;
    }
    return lp;
}

extern "C" void kernel_launch(void* const* d_in, const int* in_sizes, int n_in,
                              void* d_out, int out_size)
{
    (void)n_in; (void)out_size;
    const float* xyzs   = (const float*)d_in[0];
    const float* tables = (const float*)d_in[1];
    int N = in_sizes[0] / 3;

    cudaMemcpyToSymbolAsync(cW1, d_in[2], 32 * 64 * sizeof(float), 0,
                            cudaMemcpyDeviceToDevice, 0);
    cudaMemcpyToSymbolAsync(cW2, d_in[3], 64 * 16 * sizeof(float), 0,
                            cudaMemcpyDeviceToDevice, 0);

    LevelParams lp = make_level_params();

    int gridN = (N + BLK - 1) / BLK;
    hashgrid_mlp_kernel<<<gridN, BLK>>>(xyzs, tables, (float*)d_out, N, lp);
}

// round 6
// speedup vs baseline: 1.2173x; 1.0007x over previous
#include <cuda_runtime.h>
#include <math.h>

// ---------------- problem constants ----------------
#define NLEV   16
#define TBL    524288u          // T = 2^19 entries per level
#define TMASK  (TBL - 1u)
#define HP1    2654435761u
#define HP2    805459861u

typedef unsigned long long ull;

// MLP weights in constant memory (warp-uniform -> LDCU, keeps LSU free)
__constant__ __align__(16) float cW1[32 * 64];
__constant__ __align__(16) float cW2[64 * 16];

struct LevelParams {
    float    resf[NLEV];   // (float)res[l]
    unsigned s[NLEV];      // res[l] + 1  (dense stride)
    unsigned dense[NLEV];  // (res+1)^3 <= T ?
};

// ---------------- packed f32x2 helpers ----------------
__device__ __forceinline__ ull pack2(float v) {
    ull r; unsigned u = __float_as_uint(v);
    asm("mov.b64 %0, {%1,%1};" : "=l"(r) : "r"(u));
    return r;
}
__device__ __forceinline__ ull fma2(ull a, ull b, ull c) {
    ull d;
    asm("fma.rn.f32x2 %0, %1, %2, %3;" : "=l"(d) : "l"(a), "l"(b), "l"(c));
    return d;
}
__device__ __forceinline__ float2 unpack2(ull v) {
    unsigned lo, hi;
    asm("mov.b64 {%0,%1}, %2;" : "=r"(lo), "=r"(hi) : "l"(v));
    return make_float2(__uint_as_float(lo), __uint_as_float(hi));
}

// Dual-path paired gather, alignment-safe (proven correct since round 4).
__device__ __forceinline__ void gather_pair(const float2* __restrict__ tab,
                                            unsigned a0, unsigned a1,
                                            unsigned adj,
                                            float& v0x, float& v0y,
                                            float& v1x, float& v1y) {
    const float4* pa = reinterpret_cast<const float4*>(tab + (a0 & ~1u));
    float qx, qy, qz, qw;
    asm volatile("{\n\t"
                 ".reg .pred p;\n\t"
                 "setp.ne.u32 p, %4, 0;\n\t"
                 "@p  ld.global.nc.v4.f32 {%0,%1,%2,%3}, [%5];\n\t"
                 "@!p ld.global.nc.v2.f32 {%0,%1}, [%6];\n\t"
                 "@!p ld.global.nc.v2.f32 {%2,%3}, [%7];\n\t"
                 "}"
                 : "=f"(qx), "=f"(qy), "=f"(qz), "=f"(qw)
                 : "r"(adj), "l"(pa), "l"(tab + a0), "l"(tab + a1));
    bool swap = (adj != 0u) && ((a0 & 1u) != 0u);
    v0x = swap ? qz : qx;
    v0y = swap ? qw : qy;
    v1x = swap ? qx : qz;
    v1y = swap ? qy : qw;
}

__device__ __forceinline__ float clip01(float v) {
    return fminf(fmaxf((v + 1.0f) * 0.5f, 0.0f), 1.0f);
}

// ---------------- fused kernel: hashgrid encode + MLP ----------------
#define BLK 256

__global__ void __launch_bounds__(BLK, 3)
hashgrid_mlp_kernel(const float* __restrict__ xyzs,
                    const float* __restrict__ tables,
                    float* __restrict__ out,
                    int N, LevelParams lp)
{
    // One 32KB buffer, used as:
    //   phase 1: senc[16][BLK] float2  (per-thread private column -> no sync)
    //   phase 2: sgeo[BLK*15] float    (coalesced geo staging)
    __shared__ __align__(16) char sbuf[NLEV * BLK * 8];
    float2* senc = reinterpret_cast<float2*>(sbuf);
    float*  sgeo = reinterpret_cast<float*>(sbuf);

    int pid = blockIdx.x * BLK + threadIdx.x;
    bool active = (pid < N);
    unsigned tid = threadIdx.x;

    float o[16];

    if (active) {
        float x = xyzs[3 * pid + 0];
        float y = xyzs[3 * pid + 1];
        float z = xyzs[3 * pid + 2];
        float x01 = clip01(x), y01 = clip01(y), z01 = clip01(z);

        // ---------------- gather phase: enc -> smem ----------------
#pragma unroll
        for (int l = 0; l < NLEV; l++) {
            const float2* __restrict__ tab =
                reinterpret_cast<const float2*>(tables) + (size_t)l * TBL;

            float rf = lp.resf[l];
            float px = x01 * rf, py = y01 * rf, pz = z01 * rf;
            float fpx = floorf(px), fpy = floorf(py), fpz = floorf(pz);
            float fx = px - fpx, fy = py - fpy, fz = pz - fpz;
            unsigned ix = (unsigned)fpx, iy = (unsigned)fpy, iz = (unsigned)fpz;
            float wx0 = 1.0f - fx, wy0 = 1.0f - fy, wz0 = 1.0f - fz;

            unsigned i0a[4], i1a[4];
            float    wyz[4];
            if (lp.dense[l]) {
                unsigned s = lp.s[l];
#pragma unroll
                for (int k = 0; k < 2; k++) {
#pragma unroll
                    for (int j = 0; j < 2; j++) {
                        unsigned a = s * ((iy + (unsigned)j) + s * (iz + (unsigned)k));
                        int c = k * 2 + j;
                        i0a[c] = ix + a;
                        i1a[c] = ix + 1u + a;
                        wyz[c] = (j ? fy : wy0) * (k ? fz : wz0);
                    }
                }
            } else {
                unsigned hy0 = iy * HP1;
                unsigned hz0 = iz * HP2;
#pragma unroll
                for (int k = 0; k < 2; k++) {
#pragma unroll
                    for (int j = 0; j < 2; j++) {
                        unsigned a = (hy0 + (j ? HP1 : 0u)) ^ (hz0 + (k ? HP2 : 0u));
                        int c = k * 2 + j;
                        i0a[c] = (ix ^ a) & TMASK;
                        i1a[c] = ((ix + 1u) ^ a) & TMASK;
                        wyz[c] = (j ? fy : wy0) * (k ? fz : wz0);
                    }
                }
            }

            float v0x[4], v0y[4], v1x[4], v1y[4];
#pragma unroll
            for (int c = 0; c < 4; c++) {
                unsigned adj = ((i0a[c] ^ i1a[c]) == 1u) ? 1u : 0u;
                gather_pair(tab, i0a[c], i1a[c], adj,
                            v0x[c], v0y[c], v1x[c], v1y[c]);
            }

            float e0 = 0.0f, e1 = 0.0f;
#pragma unroll
            for (int c = 0; c < 4; c++) {
                float w0 = wx0 * wyz[c];
                float w1 = fx  * wyz[c];
                e0 = fmaf(w0, v0x[c], fmaf(w1, v1x[c], e0));
                e1 = fmaf(w0, v0y[c], fmaf(w1, v1y[c], e1));
            }
            senc[l * BLK + tid] = make_float2(e0, e1);
        }

        // ---------------- MLP: two 32-wide hidden chunks ----------------
        ull op[8];
#pragma unroll
        for (int j = 0; j < 8; j++) op[j] = 0ull;

#pragma unroll
        for (int half = 0; half < 2; half++) {
            // layer 1 partial: hidden columns [32*half, 32*half+32)
            ull hp[16];
#pragma unroll
            for (int j = 0; j < 16; j++) hp[j] = 0ull;

#pragma unroll
            for (int ip = 0; ip < 16; ip++) {
                float2 e = senc[ip * BLK + tid];
                ull e0 = pack2(e.x), e1 = pack2(e.y);
                const ulonglong2* r0 = reinterpret_cast<const ulonglong2*>(
                    cW1 + (2 * ip) * 64 + 32 * half);
                const ulonglong2* r1 = reinterpret_cast<const ulonglong2*>(
                    cW1 + (2 * ip + 1) * 64 + 32 * half);
#pragma unroll
                for (int j = 0; j < 8; j++) {
                    ulonglong2 wa = r0[j];
                    ulonglong2 wb = r1[j];
                    hp[2 * j]     = fma2(e0, wa.x, hp[2 * j]);
                    hp[2 * j + 1] = fma2(e0, wa.y, hp[2 * j + 1]);
                    hp[2 * j]     = fma2(e1, wb.x, hp[2 * j]);
                    hp[2 * j + 1] = fma2(e1, wb.y, hp[2 * j + 1]);
                }
            }

            // relu + layer 2 accumulation, consuming hp immediately
#pragma unroll
            for (int j = 0; j < 16; j++) {
                float2 p = unpack2(hp[j]);
                ull eh0 = pack2(fmaxf(p.x, 0.0f));
                ull eh1 = pack2(fmaxf(p.y, 0.0f));
                int i2 = 32 * half + 2 * j;
                const ulonglong2* w0 =
                    reinterpret_cast<const ulonglong2*>(cW2 + i2 * 16);
                const ulonglong2* w1 = w0 + 4;
#pragma unroll
                for (int q = 0; q < 4; q++) {
                    ulonglong2 a = w0[q];
                    ulonglong2 b = w1[q];
                    op[2 * q]     = fma2(eh0, a.x, op[2 * q]);
                    op[2 * q + 1] = fma2(eh0, a.y, op[2 * q + 1]);
                    op[2 * q]     = fma2(eh1, b.x, op[2 * q]);
                    op[2 * q + 1] = fma2(eh1, b.y, op[2 * q + 1]);
                }
            }
        }

#pragma unroll
        for (int j = 0; j < 8; j++) {
            float2 p = unpack2(op[j]);
            o[2 * j]     = p.x;
            o[2 * j + 1] = p.y;
        }

        out[pid] = expf(o[0]);          // coalesced sigma store
    }

    __syncthreads();                     // senc dead -> reuse buffer for geo

    if (active) {
#pragma unroll
        for (int k = 0; k < 15; k++)
            sgeo[tid * 15 + k] = o[k + 1];
    }
    __syncthreads();

    // cooperative coalesced store of this block's geo region
    int base = blockIdx.x * BLK;
    int nPts = min(BLK, N - base);
    if (nPts <= 0) return;
    float* gbase = out + (size_t)N + (size_t)base * 15;
    int total = nPts * 15;
    if (nPts == BLK && ((((size_t)gbase) & 15u) == 0)) {
        float4* g4 = reinterpret_cast<float4*>(gbase);
        const float4* s4 = reinterpret_cast<const float4*>(sgeo);
        int n4 = total / 4;  // 960
        for (int t = tid; t < n4; t += BLK) g4[t] = s4[t];
    } else {
        for (int t = tid; t < total; t += BLK) gbase[t] = sgeo[t];
    }
}

// ---------------- host ----------------
static LevelParams make_level_params()
{
    LevelParams lp;
    double pls = exp(log(2048.0 / 16.0) / (double)(NLEV - 1));
    for (int l = 0; l < NLEV; l++) {
        int r = (int)ceil(16.0 * pow(pls, (double)l));
        lp.resf[l]  = (float)r;
        lp.s[l]     = (unsigned)(r + 1);
        long long s = (long long)(r + 1);
        lp.dense[l] = (s * s * s <= (long long)TBL) ? 1u : 0u;
    }
    return lp;
}

extern "C" void kernel_launch(void* const* d_in, const int* in_sizes, int n_in,
                              void* d_out, int out_size)
{
    (void)n_in; (void)out_size;
    const float* xyzs   = (const float*)d_in[0];
    const float* tables = (const float*)d_in[1];
    int N = in_sizes[0] / 3;

    cudaMemcpyToSymbolAsync(cW1, d_in[2], 32 * 64 * sizeof(float), 0,
                            cudaMemcpyDeviceToDevice, 0);
    cudaMemcpyToSymbolAsync(cW2, d_in[3], 64 * 16 * sizeof(float), 0,
                            cudaMemcpyDeviceToDevice, 0);

    LevelParams lp = make_level_params();

    int gridN = (N + BLK - 1) / BLK;
    hashgrid_mlp_kernel<<<gridN, BLK>>>(xyzs, tables, (float*)d_out, N, lp);
}